// round 6
// baseline (speedup 1.0000x reference)
#include <cuda_runtime.h>
#include <cstdint>

// BoltzmannRouter fused kernel (round 5: 512 threads, 16 warps/SM, R3 mapping)
// x: [N=16384, D=2048] f32, gate_w: [64, D] f32, out: [N, 64] f32

#define D_DIM 2048
#define E_DIM 64
#define BT    128            // tokens per block
#define TK    16             // K-chunk
#define NCHUNK (D_DIM / TK)  // 128
#define N_ACTIVE 44
#define XS_STRIDE 132        // floats; 16B-aligned rows
#define WS_STRIDE 68
#define SC_STRIDE 66         // even -> u64-aligned score stores

#define FMA2(acc, a, b) \
    asm("fma.rn.f32x2 %0, %1, %2, %0;" : "+l"(acc) : "l"(a), "l"(b))
#define DUP64(d, s) \
    asm("mov.b64 %0, {%1, %1};" : "=l"(d) : "r"(__float_as_uint(s)))

__global__ __launch_bounds__(512, 1)
void boltzmann_router_kernel(const float* __restrict__ x,
                             const float* __restrict__ w,
                             float* __restrict__ out)
{
    // GEMM tiles and the score buffer alias the same storage (33792 B).
    __shared__ __align__(16) unsigned char smem_raw[BT * SC_STRIDE * 4];
    float* xs = (float*)smem_raw;                                // [2][TK][XS_STRIDE]
    float* ws = (float*)(smem_raw + 2 * TK * XS_STRIDE * 4);     // [2][TK][WS_STRIDE]
    float* sc = (float*)smem_raw;                                // [BT][SC_STRIDE]

    const int tid  = threadIdx.x;
    const int lane = tid & 31;
    const int warp = tid >> 5;          // 16 warps
    const int e0   = (warp & 7) * 8;    // this warp's 8 experts
    const int tBase = (warp >> 3) * 64; // this warp's 64-token half
    const int tok0 = blockIdx.x * BT;

    // acc2[i][j]: token tBase+lane*2+i, expert pair (e0+2j, e0+2j+1)
    unsigned long long acc2[2][4];
    #pragma unroll
    for (int i = 0; i < 2; i++)
        #pragma unroll
        for (int j = 0; j < 4; j++) acc2[i][j] = 0ULL;

    // loader coords (512 threads)
    const int xt  = tid >> 2;      // token 0..127
    const int xc4 = tid & 3;       // float4 index within 16-k chunk
    const int we  = (tid & 255) >> 2;  // expert 0..63 (threads 0..255 only)
    const int wc4 = tid & 3;
    const bool wload = tid < 256;

    float4 rx, rw;

    // ---- prefetch chunk 0 ----
    rx = *reinterpret_cast<const float4*>(
             x + (size_t)(tok0 + xt) * D_DIM + xc4 * 4);
    if (wload)
        rw = *reinterpret_cast<const float4*>(
                 w + (size_t)we * D_DIM + wc4 * 4);

    // ---- store chunk 0 into buffer 0 (transposed) ----
    {
        float* xr = xs + (xc4 * 4) * XS_STRIDE + xt;
        xr[0 * XS_STRIDE] = rx.x; xr[1 * XS_STRIDE] = rx.y;
        xr[2 * XS_STRIDE] = rx.z; xr[3 * XS_STRIDE] = rx.w;
        if (wload) {
            float* wr = ws + (wc4 * 4) * WS_STRIDE + we;
            wr[0 * WS_STRIDE] = rw.x; wr[1 * WS_STRIDE] = rw.y;
            wr[2 * WS_STRIDE] = rw.z; wr[3 * WS_STRIDE] = rw.w;
        }
    }
    __syncthreads();

    for (int c = 0; c < NCHUNK; c++) {
        const int buf = c & 1;

        // prefetch chunk c+1 from global (overlaps compute)
        if (c + 1 < NCHUNK) {
            rx = *reinterpret_cast<const float4*>(
                     x + (size_t)(tok0 + xt) * D_DIM + (c + 1) * TK + xc4 * 4);
            if (wload)
                rw = *reinterpret_cast<const float4*>(
                         w + (size_t)we * D_DIM + (c + 1) * TK + wc4 * 4);
        }

        // ---- compute on buffer buf ----
        const float* xbase = xs + buf * TK * XS_STRIDE + tBase + lane * 2;
        const float* wbase = ws + buf * TK * WS_STRIDE + e0;
        #pragma unroll
        for (int kk = 0; kk < TK; kk++) {
            float2 xf = *reinterpret_cast<const float2*>(xbase + kk * XS_STRIDE);
            // warp-uniform (broadcast) loads of this warp's 8 experts
            ulonglong2 wv0 = *reinterpret_cast<const ulonglong2*>(wbase + kk * WS_STRIDE);
            ulonglong2 wv1 = *reinterpret_cast<const ulonglong2*>(wbase + kk * WS_STRIDE + 4);
            unsigned long long a0, a1;
            DUP64(a0, xf.x); DUP64(a1, xf.y);
            FMA2(acc2[0][0], a0, wv0.x); FMA2(acc2[0][1], a0, wv0.y);
            FMA2(acc2[0][2], a0, wv1.x); FMA2(acc2[0][3], a0, wv1.y);
            FMA2(acc2[1][0], a1, wv0.x); FMA2(acc2[1][1], a1, wv0.y);
            FMA2(acc2[1][2], a1, wv1.x); FMA2(acc2[1][3], a1, wv1.y);
        }

        // ---- store chunk c+1 into other buffer ----
        if (c + 1 < NCHUNK) {
            // safe without a pre-sync: last readers of buf^1 finished before
            // the sync that ended iteration c-1.
            float* xr = xs + (buf ^ 1) * TK * XS_STRIDE + (xc4 * 4) * XS_STRIDE + xt;
            xr[0 * XS_STRIDE] = rx.x; xr[1 * XS_STRIDE] = rx.y;
            xr[2 * XS_STRIDE] = rx.z; xr[3 * XS_STRIDE] = rx.w;
            if (wload) {
                float* wr = ws + (buf ^ 1) * TK * WS_STRIDE + (wc4 * 4) * WS_STRIDE + we;
                wr[0 * WS_STRIDE] = rw.x; wr[1 * WS_STRIDE] = rw.y;
                wr[2 * WS_STRIDE] = rw.z; wr[3 * WS_STRIDE] = rw.w;
            }
            __syncthreads();
        }
    }

    // ---- all compute done; overwrite aliased smem with scaled scores ----
    __syncthreads();
    const float INV_TEMP = 0.36787944117144233f;  // 1/e
    #pragma unroll
    for (int i = 0; i < 2; i++) {
        int t = tBase + lane * 2 + i;
        #pragma unroll
        for (int j = 0; j < 4; j++) {
            unsigned int lo = (unsigned int)(acc2[i][j]);
            unsigned int hi = (unsigned int)(acc2[i][j] >> 32);
            sc[t * SC_STRIDE + e0 + 2 * j]     = __uint_as_float(lo) * INV_TEMP;
            sc[t * SC_STRIDE + e0 + 2 * j + 1] = __uint_as_float(hi) * INV_TEMP;
        }
    }
    __syncthreads();

    // ---- epilogue: one warp per 8 tokens (16 warps x 8 = 128) ----
    for (int tt = 0; tt < 8; tt++) {
        int t = warp * 8 + tt;
        float s0 = sc[t * SC_STRIDE + lane];
        float s1 = sc[t * SC_STRIDE + 32 + lane];

        float m = fmaxf(s0, s1);
        #pragma unroll
        for (int o = 16; o > 0; o >>= 1)
            m = fmaxf(m, __shfl_xor_sync(0xFFFFFFFFu, m, o));

        float e0v = __expf(s0 - m);
        float e1v = __expf(s1 - m);
        float z = e0v + e1v;
        #pragma unroll
        for (int o = 16; o > 0; o >>= 1)
            z += __shfl_xor_sync(0xFFFFFFFFu, z, o);

        // rank = #{j : s_j > s_i, ties broken by lower index}
        int c0 = 0, c1 = 0;
        #pragma unroll 16
        for (int j = 0; j < E_DIM; j++) {
            float sj = sc[t * SC_STRIDE + j];
            c0 += (sj > s0) || (sj == s0 && j < lane);
            c1 += (sj > s1) || (sj == s1 && j < lane + 32);
        }
        bool keep0 = c0 < N_ACTIVE;
        bool keep1 = c1 < N_ACTIVE;

        float sk = (keep0 ? e0v : 0.0f) + (keep1 ? e1v : 0.0f);
        #pragma unroll
        for (int o = 16; o > 0; o >>= 1)
            sk += __shfl_xor_sync(0xFFFFFFFFu, sk, o);

        float inv = 1.0f / (sk + 1e-8f * z);
        size_t base = (size_t)(tok0 + t) * E_DIM;
        out[base + lane]      = keep0 ? e0v * inv : 0.0f;
        out[base + lane + 32] = keep1 ? e1v * inv : 0.0f;
    }
}

extern "C" void kernel_launch(void* const* d_in, const int* in_sizes, int n_in,
                              void* d_out, int out_size)
{
    const float* x = (const float*)d_in[0];   // [N, 2048]
    const float* w = (const float*)d_in[1];   // [64, 2048]
    float* out     = (float*)d_out;           // [N, 64]
    int ntok = in_sizes[0] / D_DIM;           // 16384
    boltzmann_router_kernel<<<ntok / BT, 512>>>(x, w, out);
}

// round 7
// speedup vs baseline: 1.5434x; 1.5434x over previous
#include <cuda_runtime.h>
#include <cstdint>

// BoltzmannRouter fused kernel (round 6: R3 shape + explicit SW pipelining)
// x: [N=16384, D=2048] f32, gate_w: [64, D] f32, out: [N, 64] f32

#define D_DIM 2048
#define E_DIM 64
#define BT    128            // tokens per block
#define TK    16             // K-chunk
#define NCHUNK (D_DIM / TK)  // 128
#define N_ACTIVE 44
#define XS_STRIDE 132        // floats; 16B-aligned rows
#define WS_STRIDE 68
#define SC_STRIDE 66         // even -> u64-aligned score stores

#define FMA2(acc, a, b) \
    asm("fma.rn.f32x2 %0, %1, %2, %0;" : "+l"(acc) : "l"(a), "l"(b))
#define DUP64(d, s) \
    asm("mov.b64 %0, {%1, %1};" : "=l"(d) : "r"(__float_as_uint(s)))

__global__ __launch_bounds__(256, 1)
void boltzmann_router_kernel(const float* __restrict__ x,
                             const float* __restrict__ w,
                             float* __restrict__ out)
{
    // GEMM tiles and the score buffer alias the same storage (33792 B).
    __shared__ __align__(16) unsigned char smem_raw[BT * SC_STRIDE * 4];
    float* xs = (float*)smem_raw;                                // [2][TK][XS_STRIDE]
    float* ws = (float*)(smem_raw + 2 * TK * XS_STRIDE * 4);     // [2][TK][WS_STRIDE]
    float* sc = (float*)smem_raw;                                // [BT][SC_STRIDE]

    const int tid  = threadIdx.x;
    const int lane = tid & 31;
    const int warp = tid >> 5;          // 8 warps
    const int e0   = warp * 8;          // this warp's 8 experts
    const int tok0 = blockIdx.x * BT;

    // acc2[i][j]: token lane*4+i, expert pair (e0+2j, e0+2j+1)
    unsigned long long acc2[4][4];
    #pragma unroll
    for (int i = 0; i < 4; i++)
        #pragma unroll
        for (int j = 0; j < 4; j++) acc2[i][j] = 0ULL;

    // loader coords
    const int xt  = tid >> 2;      // token 0..63 (second load adds 64)
    const int xc4 = tid & 3;       // float4 index within 16-k chunk
    const int we  = tid >> 2;      // expert 0..63
    const int wc4 = tid & 3;

    float4 rx0, rx1, rw;

    // ---- prefetch chunk 0 ----
    {
        const float* xb = x + (size_t)(tok0 + xt) * D_DIM + xc4 * 4;
        rx0 = *reinterpret_cast<const float4*>(xb);
        rx1 = *reinterpret_cast<const float4*>(xb + (size_t)64 * D_DIM);
        rw  = *reinterpret_cast<const float4*>(w + (size_t)we * D_DIM + wc4 * 4);
    }
    // ---- store chunk 0 into buffer 0 (transposed) ----
    {
        float* xr = xs + (xc4 * 4) * XS_STRIDE;
        xr[0 * XS_STRIDE + xt] = rx0.x; xr[1 * XS_STRIDE + xt] = rx0.y;
        xr[2 * XS_STRIDE + xt] = rx0.z; xr[3 * XS_STRIDE + xt] = rx0.w;
        xr[0 * XS_STRIDE + 64 + xt] = rx1.x; xr[1 * XS_STRIDE + 64 + xt] = rx1.y;
        xr[2 * XS_STRIDE + 64 + xt] = rx1.z; xr[3 * XS_STRIDE + 64 + xt] = rx1.w;
        float* wr = ws + (wc4 * 4) * WS_STRIDE;
        wr[0 * WS_STRIDE + we] = rw.x; wr[1 * WS_STRIDE + we] = rw.y;
        wr[2 * WS_STRIDE + we] = rw.z; wr[3 * WS_STRIDE + we] = rw.w;
    }
    __syncthreads();

    for (int c = 0; c < NCHUNK; c++) {
        const int buf = c & 1;

        // prefetch chunk c+1 from global (overlaps compute)
        if (c + 1 < NCHUNK) {
            const float* xb = x + (size_t)(tok0 + xt) * D_DIM + (c + 1) * TK + xc4 * 4;
            rx0 = *reinterpret_cast<const float4*>(xb);
            rx1 = *reinterpret_cast<const float4*>(xb + (size_t)64 * D_DIM);
            rw  = *reinterpret_cast<const float4*>(
                      w + (size_t)we * D_DIM + (c + 1) * TK + wc4 * 4);
        }

        // ---- compute on buffer buf, software-pipelined over k ----
        const float* xbase = xs + buf * TK * XS_STRIDE + lane * 4;
        const float* wbase = ws + buf * TK * WS_STRIDE + e0;

        // stage k=0
        float4     xf  = *reinterpret_cast<const float4*>(xbase);
        ulonglong2 wva = *reinterpret_cast<const ulonglong2*>(wbase);
        ulonglong2 wvb = *reinterpret_cast<const ulonglong2*>(wbase + 4);

        #pragma unroll
        for (int kk = 0; kk < TK - 1; kk++) {
            // issue next k's shared loads BEFORE this k's FMAs
            float4     xf_n  = *reinterpret_cast<const float4*>(xbase + (kk + 1) * XS_STRIDE);
            ulonglong2 wva_n = *reinterpret_cast<const ulonglong2*>(wbase + (kk + 1) * WS_STRIDE);
            ulonglong2 wvb_n = *reinterpret_cast<const ulonglong2*>(wbase + (kk + 1) * WS_STRIDE + 4);

            unsigned long long a0, a1, a2, a3;
            DUP64(a0, xf.x); DUP64(a1, xf.y); DUP64(a2, xf.z); DUP64(a3, xf.w);
            FMA2(acc2[0][0], a0, wva.x); FMA2(acc2[0][1], a0, wva.y);
            FMA2(acc2[0][2], a0, wvb.x); FMA2(acc2[0][3], a0, wvb.y);
            FMA2(acc2[1][0], a1, wva.x); FMA2(acc2[1][1], a1, wva.y);
            FMA2(acc2[1][2], a1, wvb.x); FMA2(acc2[1][3], a1, wvb.y);
            FMA2(acc2[2][0], a2, wva.x); FMA2(acc2[2][1], a2, wva.y);
            FMA2(acc2[2][2], a2, wvb.x); FMA2(acc2[2][3], a2, wvb.y);
            FMA2(acc2[3][0], a3, wva.x); FMA2(acc2[3][1], a3, wva.y);
            FMA2(acc2[3][2], a3, wvb.x); FMA2(acc2[3][3], a3, wvb.y);

            xf = xf_n; wva = wva_n; wvb = wvb_n;
        }
        // final k (no prefetch)
        {
            unsigned long long a0, a1, a2, a3;
            DUP64(a0, xf.x); DUP64(a1, xf.y); DUP64(a2, xf.z); DUP64(a3, xf.w);
            FMA2(acc2[0][0], a0, wva.x); FMA2(acc2[0][1], a0, wva.y);
            FMA2(acc2[0][2], a0, wvb.x); FMA2(acc2[0][3], a0, wvb.y);
            FMA2(acc2[1][0], a1, wva.x); FMA2(acc2[1][1], a1, wva.y);
            FMA2(acc2[1][2], a1, wvb.x); FMA2(acc2[1][3], a1, wvb.y);
            FMA2(acc2[2][0], a2, wva.x); FMA2(acc2[2][1], a2, wva.y);
            FMA2(acc2[2][2], a2, wvb.x); FMA2(acc2[2][3], a2, wvb.y);
            FMA2(acc2[3][0], a3, wva.x); FMA2(acc2[3][1], a3, wva.y);
            FMA2(acc2[3][2], a3, wvb.x); FMA2(acc2[3][3], a3, wvb.y);
        }

        // ---- store chunk c+1 into other buffer ----
        if (c + 1 < NCHUNK) {
            // safe without a pre-sync: last readers of buf^1 finished before
            // the sync that ended iteration c-1.
            float* xr = xs + (buf ^ 1) * TK * XS_STRIDE + (xc4 * 4) * XS_STRIDE;
            xr[0 * XS_STRIDE + xt] = rx0.x; xr[1 * XS_STRIDE + xt] = rx0.y;
            xr[2 * XS_STRIDE + xt] = rx0.z; xr[3 * XS_STRIDE + xt] = rx0.w;
            xr[0 * XS_STRIDE + 64 + xt] = rx1.x; xr[1 * XS_STRIDE + 64 + xt] = rx1.y;
            xr[2 * XS_STRIDE + 64 + xt] = rx1.z; xr[3 * XS_STRIDE + 64 + xt] = rx1.w;
            float* wr = ws + (buf ^ 1) * TK * WS_STRIDE + (wc4 * 4) * WS_STRIDE;
            wr[0 * WS_STRIDE + we] = rw.x; wr[1 * WS_STRIDE + we] = rw.y;
            wr[2 * WS_STRIDE + we] = rw.z; wr[3 * WS_STRIDE + we] = rw.w;
            __syncthreads();
        }
    }

    // ---- all compute done; overwrite aliased smem with scaled scores ----
    __syncthreads();
    const float INV_TEMP = 0.36787944117144233f;  // 1/e
    #pragma unroll
    for (int i = 0; i < 4; i++) {
        int t = lane * 4 + i;
        #pragma unroll
        for (int j = 0; j < 4; j++) {
            unsigned int lo = (unsigned int)(acc2[i][j]);
            unsigned int hi = (unsigned int)(acc2[i][j] >> 32);
            sc[t * SC_STRIDE + e0 + 2 * j]     = __uint_as_float(lo) * INV_TEMP;
            sc[t * SC_STRIDE + e0 + 2 * j + 1] = __uint_as_float(hi) * INV_TEMP;
        }
    }
    __syncthreads();

    // ---- epilogue: one warp per 16 tokens ----
    for (int tt = 0; tt < 16; tt++) {
        int t = warp * 16 + tt;
        float s0 = sc[t * SC_STRIDE + lane];
        float s1 = sc[t * SC_STRIDE + 32 + lane];

        float m = fmaxf(s0, s1);
        #pragma unroll
        for (int o = 16; o > 0; o >>= 1)
            m = fmaxf(m, __shfl_xor_sync(0xFFFFFFFFu, m, o));

        float e0v = __expf(s0 - m);
        float e1v = __expf(s1 - m);
        float z = e0v + e1v;
        #pragma unroll
        for (int o = 16; o > 0; o >>= 1)
            z += __shfl_xor_sync(0xFFFFFFFFu, z, o);

        // rank = #{j : s_j > s_i, ties broken by lower index}
        int c0 = 0, c1 = 0;
        #pragma unroll 16
        for (int j = 0; j < E_DIM; j++) {
            float sj = sc[t * SC_STRIDE + j];
            c0 += (sj > s0) || (sj == s0 && j < lane);
            c1 += (sj > s1) || (sj == s1 && j < lane + 32);
        }
        bool keep0 = c0 < N_ACTIVE;
        bool keep1 = c1 < N_ACTIVE;

        float sk = (keep0 ? e0v : 0.0f) + (keep1 ? e1v : 0.0f);
        #pragma unroll
        for (int o = 16; o > 0; o >>= 1)
            sk += __shfl_xor_sync(0xFFFFFFFFu, sk, o);

        float inv = 1.0f / (sk + 1e-8f * z);
        size_t base = (size_t)(tok0 + t) * E_DIM;
        out[base + lane]      = keep0 ? e0v * inv : 0.0f;
        out[base + lane + 32] = keep1 ? e1v * inv : 0.0f;
    }
}

extern "C" void kernel_launch(void* const* d_in, const int* in_sizes, int n_in,
                              void* d_out, int out_size)
{
    const float* x = (const float*)d_in[0];   // [N, 2048]
    const float* w = (const float*)d_in[1];   // [64, 2048]
    float* out     = (float*)d_out;           // [N, 64]
    int ntok = in_sizes[0] / D_DIM;           // 16384
    boltzmann_router_kernel<<<ntok / BT, 256>>>(x, w, out);
}